// round 5
// baseline (speedup 1.0000x reference)
#include <cuda_runtime.h>
#include <stdint.h>

#define D 128
#define MAX_N 50048
#define MAX_E 600064

// Scratch (device globals — no allocation). All fully rewritten each launch.
__device__ float g_h[(size_t)MAX_N * D];   // h' = (x@W) * dis[row]
__device__ float g_dis[MAX_N];
__device__ int   g_cnt[MAX_N];             // edge in-degree (no self-loop)
__device__ int   g_rowstart[MAX_N];
__device__ int   g_cursor[MAX_N];
__device__ int   g_csrc[MAX_E];            // CSR: src ids grouped by dst

typedef unsigned long long u64;

__device__ __forceinline__ void fma2(u64 &acc, u64 a, u64 b) {
    asm("fma.rn.f32x2 %0, %1, %2, %0;" : "+l"(acc) : "l"(a), "l"(b));
}
__device__ __forceinline__ u64 pack2(float v) {
    u64 r; asm("mov.b64 %0, {%1, %1};" : "=l"(r) : "f"(v)); return r;
}
__device__ __forceinline__ float2 unpack2(u64 v) {
    float2 f; asm("mov.b64 {%0, %1}, %2;" : "=f"(f.x), "=f"(f.y) : "l"(v)); return f;
}

// ---------------- degree / norm ----------------
__global__ void k_cnt_init(int n) {
    int i = blockIdx.x * blockDim.x + threadIdx.x;
    if (i < n) g_cnt[i] = 0;
}
__global__ void k_cnt_count(const int* __restrict__ ei, int e) {
    int i = blockIdx.x * blockDim.x + threadIdx.x;
    if (i < e) atomicAdd(&g_cnt[ei[e + i]], 1);        // dst
}
__global__ void k_dis(int n) {
    int i = blockIdx.x * blockDim.x + threadIdx.x;
    if (i < n) g_dis[i] = rsqrtf((float)(g_cnt[i] + 1));  // +1 self-loop
}

// ---------------- exclusive scan (single block) ----------------
__global__ void k_scan(int n) {
    __shared__ int part[1024];
    int tid = threadIdx.x;
    int per = (n + 1023) >> 10;
    int start = tid * per;
    int end = min(start + per, n);
    int s = 0;
    for (int i = start; i < end; i++) s += g_cnt[i];
    part[tid] = s;
    __syncthreads();
    for (int off = 1; off < 1024; off <<= 1) {
        int v = part[tid];
        int add = (tid >= off) ? part[tid - off] : 0;
        __syncthreads();
        part[tid] = v + add;
        __syncthreads();
    }
    int base = (tid == 0) ? 0 : part[tid - 1];
    for (int i = start; i < end; i++) {
        g_rowstart[i] = base;
        g_cursor[i]   = base;
        base += g_cnt[i];
    }
}

// ---------------- CSR fill ----------------
__global__ void k_fill(const int* __restrict__ ei, int e) {
    int i = blockIdx.x * blockDim.x + threadIdx.x;
    if (i < e) {
        int d = ei[e + i];
        int pos = atomicAdd(&g_cursor[d], 1);
        g_csrc[pos] = ei[i];                           // src
    }
}

// ---------------- GEMM h = x@W (FFMA2, row-pair accumulators), fused self-loop ----------------
// 128 thr, 32 rows/block. xs stored transposed xs[k][row] so row-pair x
// operands are natural LDS.64 u64 pairs (no packing). W packed 4/k.
__global__ __launch_bounds__(128, 6) void k_gemm(const float* __restrict__ x,
                                                 const float* __restrict__ W,
                                                 const float* __restrict__ b,
                                                 float* __restrict__ out, int n) {
    __shared__ float xs[D][34];          // [k][row], pad 34: LDS.64-aligned, 2-way STS conflict
    int row0 = blockIdx.x * 32;

    // load 32 rows transposed: i -> r = i>>5 (row), q = i&31 (float4 col)
#pragma unroll
    for (int it = 0; it < 8; it++) {
        int i = it * 128 + threadIdx.x;
        int r = i >> 5;
        int q = i & 31;
        int gr = row0 + r;
        float4 v = make_float4(0.f, 0.f, 0.f, 0.f);
        if (gr < n) v = *(const float4*)(x + (size_t)gr * D + (q << 2));
        xs[q * 4 + 0][r] = v.x;
        xs[q * 4 + 1][r] = v.y;
        xs[q * 4 + 2][r] = v.z;
        xs[q * 4 + 3][r] = v.w;
    }
    __syncthreads();

    int warp = threadIdx.x >> 5;         // 0..3, rows warp*8 .. +7
    int lane = threadIdx.x & 31;
    int c = lane << 2;

    u64 acc[4][4];                       // [rowpair][col]
#pragma unroll
    for (int rp = 0; rp < 4; rp++)
#pragma unroll
        for (int cc = 0; cc < 4; cc++) acc[rp][cc] = 0ULL;

#pragma unroll 4
    for (int k = 0; k < D; k++) {
        float4 wv = *(const float4*)(W + k * D + c);   // L1-resident
        u64 wd0 = pack2(wv.x), wd1 = pack2(wv.y), wd2 = pack2(wv.z), wd3 = pack2(wv.w);
        const u64* xp = (const u64*)&xs[k][warp * 8];  // 4 row-pairs (broadcast LDS.64)
        u64 x0 = xp[0], x1 = xp[1], x2 = xp[2], x3 = xp[3];
        fma2(acc[0][0], x0, wd0); fma2(acc[0][1], x0, wd1); fma2(acc[0][2], x0, wd2); fma2(acc[0][3], x0, wd3);
        fma2(acc[1][0], x1, wd0); fma2(acc[1][1], x1, wd1); fma2(acc[1][2], x1, wd2); fma2(acc[1][3], x1, wd3);
        fma2(acc[2][0], x2, wd0); fma2(acc[2][1], x2, wd1); fma2(acc[2][2], x2, wd2); fma2(acc[2][3], x2, wd3);
        fma2(acc[3][0], x3, wd0); fma2(acc[3][1], x3, wd1); fma2(acc[3][2], x3, wd2); fma2(acc[3][3], x3, wd3);
    }

    float4 bv = *(const float4*)(b + c);
#pragma unroll
    for (int rp = 0; rp < 4; rp++) {
        int gr0 = row0 + warp * 8 + rp * 2;
        float2 v0 = unpack2(acc[rp][0]);
        float2 v1 = unpack2(acc[rp][1]);
        float2 v2 = unpack2(acc[rp][2]);
        float2 v3 = unpack2(acc[rp][3]);
        float4 rA = make_float4(v0.x, v1.x, v2.x, v3.x);   // row gr0
        float4 rB = make_float4(v0.y, v1.y, v2.y, v3.y);   // row gr0+1
#pragma unroll
        for (int h2 = 0; h2 < 2; h2++) {
            int gr = gr0 + h2;
            if (gr < n) {
                float4 hv = h2 ? rB : rA;
                float di = g_dis[gr];
                float4 hp;                                  // h' = h * dis
                hp.x = hv.x * di; hp.y = hv.y * di; hp.z = hv.z * di; hp.w = hv.w * di;
                *(float4*)(g_h + (size_t)gr * D + c) = hp;
                float4 o;                                   // self: h'*dis + b
                o.x = hp.x * di + bv.x;
                o.y = hp.y * di + bv.y;
                o.z = hp.z * di + bv.z;
                o.w = hp.w * di + bv.w;
                *(float4*)(out + (size_t)gr * D + c) = o;
            }
        }
    }
}

// ---------------- gather: warp per dst, register accumulation ----------------
__global__ __launch_bounds__(256) void k_gather(float* __restrict__ out, int n) {
    int w = (blockIdx.x * blockDim.x + threadIdx.x) >> 5;
    int lane = threadIdx.x & 31;
    if (w >= n) return;
    int cnt = g_cnt[w];
    if (cnt == 0) return;
    int start = g_rowstart[w];
    float nd = g_dis[w];
    float4 acc = make_float4(0.f, 0.f, 0.f, 0.f);
    int j = 0;
    while (j < cnt) {
        int batch = min(cnt - j, 32);
        int s = (lane < batch) ? g_csrc[start + j + lane] : 0;
#pragma unroll 4
        for (int t = 0; t < batch; t++) {
            int st = __shfl_sync(0xffffffffu, s, t);
            float4 h = *(const float4*)(g_h + (size_t)st * D + (lane << 2));
            acc.x += h.x; acc.y += h.y; acc.z += h.z; acc.w += h.w;
        }
        j += batch;
    }
    float* p = out + (size_t)w * D + (lane << 2);
    float4 o = *(float4*)p;                  // has self-loop + b from gemm
    o.x += acc.x * nd; o.y += acc.y * nd; o.z += acc.z * nd; o.w += acc.w * nd;
    *(float4*)p = o;
}

extern "C" void kernel_launch(void* const* d_in, const int* in_sizes, int n_in,
                              void* d_out, int out_size) {
    const float* x  = (const float*)d_in[0];
    const int*   ei = (const int*)d_in[1];     // edge_index int32
    const float* W  = (const float*)d_in[2];
    const float* b  = (const float*)d_in[3];
    float* out = (float*)d_out;

    int n = in_sizes[0] / D;
    int e = in_sizes[1] / 2;

    k_cnt_init<<<(n + 255) / 256, 256>>>(n);
    k_cnt_count<<<(e + 255) / 256, 256>>>(ei, e);
    k_dis<<<(n + 255) / 256, 256>>>(n);
    k_scan<<<1, 1024>>>(n);
    k_fill<<<(e + 255) / 256, 256>>>(ei, e);
    k_gemm<<<(n + 31) / 32, 128>>>(x, W, b, out, n);
    k_gather<<<(n * 32 + 255) / 256, 256>>>(out, n);
}

// round 6
// speedup vs baseline: 1.8716x; 1.8716x over previous
#include <cuda_runtime.h>
#include <stdint.h>

#define D 128
#define MAX_N 50048
#define MAX_E 600064

// Scratch (device globals — no allocation). All fully rewritten each launch.
__device__ float g_h[(size_t)MAX_N * D];   // h' = (x@W) * dis[row]
__device__ float g_dis[MAX_N];
__device__ int   g_cnt[MAX_N];             // edge in-degree (no self-loop)
__device__ int   g_rowstart[MAX_N];
__device__ int   g_cursor[MAX_N];
__device__ int   g_csrc[MAX_E];            // CSR: src ids grouped by dst
__device__ int   g_total;                  // bump allocator for row ranges

typedef unsigned long long u64;

__device__ __forceinline__ void fma2(u64 &acc, u64 a, u64 b) {
    asm("fma.rn.f32x2 %0, %1, %2, %0;" : "+l"(acc) : "l"(a), "l"(b));
}
__device__ __forceinline__ u64 pack2(float v) {
    u64 r; asm("mov.b64 %0, {%1, %1};" : "=l"(r) : "f"(v)); return r;
}
__device__ __forceinline__ float2 unpack2(u64 v) {
    float2 f; asm("mov.b64 {%0, %1}, %2;" : "=f"(f.x), "=f"(f.y) : "l"(v)); return f;
}

// ---------------- degree count ----------------
__global__ void k_cnt_init(int n) {
    int i = blockIdx.x * blockDim.x + threadIdx.x;
    if (i < n) g_cnt[i] = 0;
    if (i == 0) g_total = 0;
}
__global__ void k_cnt_count(const int* __restrict__ ei, int e) {
    int i = blockIdx.x * blockDim.x + threadIdx.x;
    if (i < e) atomicAdd(&g_cnt[ei[e + i]], 1);        // dst
}

// ---------------- row-range allocation (warp-aggregated bump alloc) + dis ----------------
// CSR bases need only be disjoint + correctly sized; order is irrelevant
// (edges are binned per-dst). One atomic per warp -> full-chip parallel.
__global__ void k_offsets(int n) {
    int i = blockIdx.x * blockDim.x + threadIdx.x;
    int lane = threadIdx.x & 31;
    int c = (i < n) ? g_cnt[i] : 0;
    int s = c;
#pragma unroll
    for (int off = 1; off < 32; off <<= 1) {
        int v = __shfl_up_sync(0xffffffffu, s, off);
        if (lane >= off) s += v;
    }
    int warpTotal = __shfl_sync(0xffffffffu, s, 31);
    int base = 0;
    if (lane == 31) base = atomicAdd(&g_total, warpTotal);
    base = __shfl_sync(0xffffffffu, base, 31);
    if (i < n) {
        int rs = base + s - c;                 // exclusive prefix within warp
        g_rowstart[i] = rs;
        g_cursor[i]   = rs;
        g_dis[i] = rsqrtf((float)(c + 1));     // +1 self-loop
    }
}

// ---------------- CSR fill ----------------
__global__ void k_fill(const int* __restrict__ ei, int e) {
    int i = blockIdx.x * blockDim.x + threadIdx.x;
    if (i < e) {
        int d = ei[e + i];
        int pos = atomicAdd(&g_cursor[d], 1);
        g_csrc[pos] = ei[i];                   // src
    }
}

// ---------------- GEMM h = x@W (FFMA2, row-pair accumulators), fused self-loop ----------------
__global__ __launch_bounds__(128, 6) void k_gemm(const float* __restrict__ x,
                                                 const float* __restrict__ W,
                                                 const float* __restrict__ b,
                                                 float* __restrict__ out, int n) {
    __shared__ float xs[D][34];          // [k][row]
    int row0 = blockIdx.x * 32;

#pragma unroll
    for (int it = 0; it < 8; it++) {
        int i = it * 128 + threadIdx.x;
        int r = i >> 5;
        int q = i & 31;
        int gr = row0 + r;
        float4 v = make_float4(0.f, 0.f, 0.f, 0.f);
        if (gr < n) v = *(const float4*)(x + (size_t)gr * D + (q << 2));
        xs[q * 4 + 0][r] = v.x;
        xs[q * 4 + 1][r] = v.y;
        xs[q * 4 + 2][r] = v.z;
        xs[q * 4 + 3][r] = v.w;
    }
    __syncthreads();

    int warp = threadIdx.x >> 5;
    int lane = threadIdx.x & 31;
    int c = lane << 2;

    u64 acc[4][4];
#pragma unroll
    for (int rp = 0; rp < 4; rp++)
#pragma unroll
        for (int cc = 0; cc < 4; cc++) acc[rp][cc] = 0ULL;

#pragma unroll 4
    for (int k = 0; k < D; k++) {
        float4 wv = *(const float4*)(W + k * D + c);   // L1-resident
        u64 wd0 = pack2(wv.x), wd1 = pack2(wv.y), wd2 = pack2(wv.z), wd3 = pack2(wv.w);
        const u64* xp = (const u64*)&xs[k][warp * 8];  // 4 row-pairs (LDS.64)
        u64 x0 = xp[0], x1 = xp[1], x2 = xp[2], x3 = xp[3];
        fma2(acc[0][0], x0, wd0); fma2(acc[0][1], x0, wd1); fma2(acc[0][2], x0, wd2); fma2(acc[0][3], x0, wd3);
        fma2(acc[1][0], x1, wd0); fma2(acc[1][1], x1, wd1); fma2(acc[1][2], x1, wd2); fma2(acc[1][3], x1, wd3);
        fma2(acc[2][0], x2, wd0); fma2(acc[2][1], x2, wd1); fma2(acc[2][2], x2, wd2); fma2(acc[2][3], x2, wd3);
        fma2(acc[3][0], x3, wd0); fma2(acc[3][1], x3, wd1); fma2(acc[3][2], x3, wd2); fma2(acc[3][3], x3, wd3);
    }

    float4 bv = *(const float4*)(b + c);
#pragma unroll
    for (int rp = 0; rp < 4; rp++) {
        int gr0 = row0 + warp * 8 + rp * 2;
        float2 v0 = unpack2(acc[rp][0]);
        float2 v1 = unpack2(acc[rp][1]);
        float2 v2 = unpack2(acc[rp][2]);
        float2 v3 = unpack2(acc[rp][3]);
        float4 rA = make_float4(v0.x, v1.x, v2.x, v3.x);
        float4 rB = make_float4(v0.y, v1.y, v2.y, v3.y);
#pragma unroll
        for (int h2 = 0; h2 < 2; h2++) {
            int gr = gr0 + h2;
            if (gr < n) {
                float4 hv = h2 ? rB : rA;
                float di = g_dis[gr];
                float4 hp;
                hp.x = hv.x * di; hp.y = hv.y * di; hp.z = hv.z * di; hp.w = hv.w * di;
                *(float4*)(g_h + (size_t)gr * D + c) = hp;
                float4 o;
                o.x = hp.x * di + bv.x;
                o.y = hp.y * di + bv.y;
                o.z = hp.z * di + bv.z;
                o.w = hp.w * di + bv.w;
                *(float4*)(out + (size_t)gr * D + c) = o;
            }
        }
    }
}

// ---------------- gather: warp per dst, register accumulation ----------------
__global__ __launch_bounds__(256) void k_gather(float* __restrict__ out, int n) {
    int w = (blockIdx.x * blockDim.x + threadIdx.x) >> 5;
    int lane = threadIdx.x & 31;
    if (w >= n) return;
    int cnt = g_cnt[w];
    if (cnt == 0) return;
    int start = g_rowstart[w];
    float nd = g_dis[w];
    float4 acc = make_float4(0.f, 0.f, 0.f, 0.f);
    int j = 0;
    while (j < cnt) {
        int batch = min(cnt - j, 32);
        int s = (lane < batch) ? g_csrc[start + j + lane] : 0;
#pragma unroll 4
        for (int t = 0; t < batch; t++) {
            int st = __shfl_sync(0xffffffffu, s, t);
            float4 h = *(const float4*)(g_h + (size_t)st * D + (lane << 2));
            acc.x += h.x; acc.y += h.y; acc.z += h.z; acc.w += h.w;
        }
        j += batch;
    }
    float* p = out + (size_t)w * D + (lane << 2);
    float4 o = *(float4*)p;                  // self-loop + b from gemm
    o.x += acc.x * nd; o.y += acc.y * nd; o.z += acc.z * nd; o.w += acc.w * nd;
    *(float4*)p = o;
}

extern "C" void kernel_launch(void* const* d_in, const int* in_sizes, int n_in,
                              void* d_out, int out_size) {
    const float* x  = (const float*)d_in[0];
    const int*   ei = (const int*)d_in[1];     // edge_index int32
    const float* W  = (const float*)d_in[2];
    const float* b  = (const float*)d_in[3];
    float* out = (float*)d_out;

    int n = in_sizes[0] / D;
    int e = in_sizes[1] / 2;

    k_cnt_init<<<(n + 255) / 256, 256>>>(n);
    k_cnt_count<<<(e + 255) / 256, 256>>>(ei, e);
    k_offsets<<<(n + 255) / 256, 256>>>(n);
    k_fill<<<(e + 255) / 256, 256>>>(ei, e);
    k_gemm<<<(n + 31) / 32, 128>>>(x, W, b, out, n);
    k_gather<<<(n * 32 + 255) / 256, 256>>>(out, n);
}

// round 7
// speedup vs baseline: 2.0293x; 1.0842x over previous
#include <cuda_runtime.h>
#include <stdint.h>

#define D 128
#define MAX_N 50048
#define MAX_E 600064

// Scratch (device globals — no allocation). All fully rewritten each launch.
__device__ float g_h[(size_t)MAX_N * D];   // raw h = x@W
__device__ float g_dis[MAX_N];
__device__ int   g_cnt[MAX_N];             // edge in-degree (no self-loop)
__device__ int   g_rowstart[MAX_N];
__device__ int   g_cursor[MAX_N];
__device__ int   g_csrc[MAX_E];            // CSR: src ids grouped by dst
__device__ int   g_total;                  // bump allocator

typedef unsigned long long u64;

__device__ __forceinline__ void fma2(u64 &acc, u64 a, u64 b) {
    asm("fma.rn.f32x2 %0, %1, %2, %0;" : "+l"(acc) : "l"(a), "l"(b));
}
__device__ __forceinline__ u64 pack2(float v) {
    u64 r; asm("mov.b64 %0, {%1, %1};" : "=l"(r) : "f"(v)); return r;
}
__device__ __forceinline__ float2 unpack2(u64 v) {
    float2 f; asm("mov.b64 {%0, %1}, %2;" : "=f"(f.x), "=f"(f.y) : "l"(v)); return f;
}

// ---- streams/events for capture-safe fork/join (created at program load,
// before the harness's memory checkpoints; nothing created per-launch) ----
struct ForkCtx {
    cudaStream_t s2;
    cudaEvent_t ev_fork, ev_join;
    ForkCtx() {
        cudaStreamCreateWithFlags(&s2, cudaStreamNonBlocking);
        cudaEventCreateWithFlags(&ev_fork, cudaEventDisableTiming);
        cudaEventCreateWithFlags(&ev_join, cudaEventDisableTiming);
    }
};
static ForkCtx g_fork;

// ---------------- degree count ----------------
__global__ void k_cnt_init(int n) {
    int i = blockIdx.x * blockDim.x + threadIdx.x;
    if (i < n) g_cnt[i] = 0;
    if (i == 0) g_total = 0;
}
__global__ void k_cnt_count(const int* __restrict__ ei, int e) {
    int i = blockIdx.x * blockDim.x + threadIdx.x;
    int base = i << 2;
    if (base + 3 < e) {
        int4 d4 = *(const int4*)(ei + e + base);
        atomicAdd(&g_cnt[d4.x], 1);
        atomicAdd(&g_cnt[d4.y], 1);
        atomicAdd(&g_cnt[d4.z], 1);
        atomicAdd(&g_cnt[d4.w], 1);
    } else {
        for (int j = base; j < e; j++) atomicAdd(&g_cnt[ei[e + j]], 1);
    }
}

// ---------------- row-range allocation (warp-aggregated bump alloc) + dis ----------------
__global__ void k_offsets(int n) {
    int i = blockIdx.x * blockDim.x + threadIdx.x;
    int lane = threadIdx.x & 31;
    int c = (i < n) ? g_cnt[i] : 0;
    int s = c;
#pragma unroll
    for (int off = 1; off < 32; off <<= 1) {
        int v = __shfl_up_sync(0xffffffffu, s, off);
        if (lane >= off) s += v;
    }
    int warpTotal = __shfl_sync(0xffffffffu, s, 31);
    int base = 0;
    if (lane == 31) base = atomicAdd(&g_total, warpTotal);
    base = __shfl_sync(0xffffffffu, base, 31);
    if (i < n) {
        int rs = base + s - c;
        g_rowstart[i] = rs;
        g_cursor[i]   = rs;
        g_dis[i] = rsqrtf((float)(c + 1));     // +1 self-loop
    }
}

// ---------------- CSR fill (2 edges/thread for atomic MLP) ----------------
__global__ void k_fill(const int* __restrict__ ei, int e) {
    int i = blockIdx.x * blockDim.x + threadIdx.x;
    int base = i << 1;
    if (base + 1 < e) {
        int2 s2 = *(const int2*)(ei + base);
        int2 d2 = *(const int2*)(ei + e + base);
        int p0 = atomicAdd(&g_cursor[d2.x], 1);
        int p1 = atomicAdd(&g_cursor[d2.y], 1);
        g_csrc[p0] = s2.x;
        g_csrc[p1] = s2.y;
    } else if (base < e) {
        int d = ei[e + base];
        int pos = atomicAdd(&g_cursor[d], 1);
        g_csrc[pos] = ei[base];
    }
}

// ---------------- GEMM h = x@W (FFMA2, row-pair accumulators), raw output ----------------
__global__ __launch_bounds__(128, 6) void k_gemm(const float* __restrict__ x,
                                                 const float* __restrict__ W,
                                                 int n) {
    __shared__ float xs[D][34];          // [k][row]
    int row0 = blockIdx.x * 32;

#pragma unroll
    for (int it = 0; it < 8; it++) {
        int i = it * 128 + threadIdx.x;
        int r = i >> 5;
        int q = i & 31;
        int gr = row0 + r;
        float4 v = make_float4(0.f, 0.f, 0.f, 0.f);
        if (gr < n) v = *(const float4*)(x + (size_t)gr * D + (q << 2));
        xs[q * 4 + 0][r] = v.x;
        xs[q * 4 + 1][r] = v.y;
        xs[q * 4 + 2][r] = v.z;
        xs[q * 4 + 3][r] = v.w;
    }
    __syncthreads();

    int warp = threadIdx.x >> 5;
    int lane = threadIdx.x & 31;
    int c = lane << 2;

    u64 acc[4][4];
#pragma unroll
    for (int rp = 0; rp < 4; rp++)
#pragma unroll
        for (int cc = 0; cc < 4; cc++) acc[rp][cc] = 0ULL;

#pragma unroll 4
    for (int k = 0; k < D; k++) {
        float4 wv = *(const float4*)(W + k * D + c);   // L1-resident
        u64 wd0 = pack2(wv.x), wd1 = pack2(wv.y), wd2 = pack2(wv.z), wd3 = pack2(wv.w);
        const u64* xp = (const u64*)&xs[k][warp * 8];  // 4 row-pairs (LDS.64)
        u64 x0 = xp[0], x1 = xp[1], x2 = xp[2], x3 = xp[3];
        fma2(acc[0][0], x0, wd0); fma2(acc[0][1], x0, wd1); fma2(acc[0][2], x0, wd2); fma2(acc[0][3], x0, wd3);
        fma2(acc[1][0], x1, wd0); fma2(acc[1][1], x1, wd1); fma2(acc[1][2], x1, wd2); fma2(acc[1][3], x1, wd3);
        fma2(acc[2][0], x2, wd0); fma2(acc[2][1], x2, wd1); fma2(acc[2][2], x2, wd2); fma2(acc[2][3], x2, wd3);
        fma2(acc[3][0], x3, wd0); fma2(acc[3][1], x3, wd1); fma2(acc[3][2], x3, wd2); fma2(acc[3][3], x3, wd3);
    }

#pragma unroll
    for (int rp = 0; rp < 4; rp++) {
        int gr0 = row0 + warp * 8 + rp * 2;
        float2 v0 = unpack2(acc[rp][0]);
        float2 v1 = unpack2(acc[rp][1]);
        float2 v2 = unpack2(acc[rp][2]);
        float2 v3 = unpack2(acc[rp][3]);
        if (gr0 < n)
            *(float4*)(g_h + (size_t)gr0 * D + c) = make_float4(v0.x, v1.x, v2.x, v3.x);
        if (gr0 + 1 < n)
            *(float4*)(g_h + (size_t)(gr0 + 1) * D + c) = make_float4(v0.y, v1.y, v2.y, v3.y);
    }
}

// ---------------- gather: warp per dst, full normalization + self-loop + bias ----------------
// out[w] = (sum_{s in N(w)} h[s]*dis[s] + h[w]*dis[w]) * dis[w] + b
__global__ __launch_bounds__(256) void k_gather(const float* __restrict__ b,
                                                float* __restrict__ out, int n) {
    int w = (blockIdx.x * blockDim.x + threadIdx.x) >> 5;
    int lane = threadIdx.x & 31;
    if (w >= n) return;
    int cnt = g_cnt[w];
    int start = g_rowstart[w];
    float nd = g_dis[w];
    int c = lane << 2;

    // self-loop term
    float4 hw = *(const float4*)(g_h + (size_t)w * D + c);
    float4 acc;
    acc.x = hw.x * nd; acc.y = hw.y * nd; acc.z = hw.z * nd; acc.w = hw.w * nd;

    int j = 0;
    while (j < cnt) {
        int batch = min(cnt - j, 32);
        int s = 0; float ds = 0.f;
        if (lane < batch) {
            s = g_csrc[start + j + lane];
            ds = g_dis[s];
        }
#pragma unroll 4
        for (int t = 0; t < batch; t++) {
            int st = __shfl_sync(0xffffffffu, s, t);
            float dt = __shfl_sync(0xffffffffu, ds, t);
            float4 h = *(const float4*)(g_h + (size_t)st * D + c);
            acc.x += h.x * dt; acc.y += h.y * dt; acc.z += h.z * dt; acc.w += h.w * dt;
        }
        j += batch;
    }
    float4 bv = *(const float4*)(b + c);
    float4 o;
    o.x = acc.x * nd + bv.x;
    o.y = acc.y * nd + bv.y;
    o.z = acc.z * nd + bv.z;
    o.w = acc.w * nd + bv.w;
    *(float4*)(out + (size_t)w * D + c) = o;
}

extern "C" void kernel_launch(void* const* d_in, const int* in_sizes, int n_in,
                              void* d_out, int out_size) {
    const float* x  = (const float*)d_in[0];
    const int*   ei = (const int*)d_in[1];     // edge_index int32
    const float* W  = (const float*)d_in[2];
    const float* b  = (const float*)d_in[3];
    float* out = (float*)d_out;

    int n = in_sizes[0] / D;
    int e = in_sizes[1] / 2;

    // fork: GEMM on side stream, CSR build on main (capture) stream
    cudaEventRecord(g_fork.ev_fork, 0);
    cudaStreamWaitEvent(g_fork.s2, g_fork.ev_fork, 0);
    k_gemm<<<(n + 31) / 32, 128, 0, g_fork.s2>>>(x, W, n);

    k_cnt_init<<<(n + 255) / 256, 256>>>(n);
    k_cnt_count<<<(e / 4 + 256) / 256, 256>>>(ei, e);
    k_offsets<<<(n + 255) / 256, 256>>>(n);
    k_fill<<<(e / 2 + 256) / 256, 256>>>(ei, e);

    // join
    cudaEventRecord(g_fork.ev_join, g_fork.s2);
    cudaStreamWaitEvent(0, g_fork.ev_join, 0);

    k_gather<<<(n * 32 + 255) / 256, 256>>>(b, out, n);
}

// round 8
// speedup vs baseline: 2.0793x; 1.0247x over previous
#include <cuda_runtime.h>
#include <cuda_fp16.h>
#include <stdint.h>

#define D 128
#define MAX_N 50048
#define MAX_E 600064

// Scratch (device globals — no allocation). All fully rewritten each launch.
__device__ float   g_h[(size_t)MAX_N * D];     // raw h = x@W (fp32)
__device__ __half2 g_hh[(size_t)MAX_N * (D/2)]; // h in fp16 (gather payload)
__device__ float   g_dis[MAX_N];
__device__ int     g_cnt[MAX_N];
__device__ int     g_rowstart[MAX_N];
__device__ int     g_cursor[MAX_N];
__device__ int     g_csrc[MAX_E];
__device__ int     g_total;

typedef unsigned long long u64;

__device__ __forceinline__ void fma2(u64 &acc, u64 a, u64 b) {
    asm("fma.rn.f32x2 %0, %1, %2, %0;" : "+l"(acc) : "l"(a), "l"(b));
}
__device__ __forceinline__ u64 pack2(float v) {
    u64 r; asm("mov.b64 %0, {%1, %1};" : "=l"(r) : "f"(v)); return r;
}
__device__ __forceinline__ float2 unpack2(u64 v) {
    float2 f; asm("mov.b64 {%0, %1}, %2;" : "=f"(f.x), "=f"(f.y) : "l"(v)); return f;
}

// ---- streams/events for capture-safe fork/join (created at program load) ----
struct ForkCtx {
    cudaStream_t s2;
    cudaEvent_t ev_fork, ev_join;
    ForkCtx() {
        cudaStreamCreateWithFlags(&s2, cudaStreamNonBlocking);
        cudaEventCreateWithFlags(&ev_fork, cudaEventDisableTiming);
        cudaEventCreateWithFlags(&ev_join, cudaEventDisableTiming);
    }
};
static ForkCtx g_fork;

// ---------------- degree count ----------------
__global__ void k_cnt_init(int n) {
    int i = blockIdx.x * blockDim.x + threadIdx.x;
    if (i < n) g_cnt[i] = 0;
    if (i == 0) g_total = 0;
}
__global__ void k_cnt_count(const int* __restrict__ ei, int e) {
    int i = blockIdx.x * blockDim.x + threadIdx.x;
    int base = i << 2;
    if (base + 3 < e) {
        int4 d4 = *(const int4*)(ei + e + base);
        atomicAdd(&g_cnt[d4.x], 1);
        atomicAdd(&g_cnt[d4.y], 1);
        atomicAdd(&g_cnt[d4.z], 1);
        atomicAdd(&g_cnt[d4.w], 1);
    } else {
        for (int j = base; j < e; j++) atomicAdd(&g_cnt[ei[e + j]], 1);
    }
}

// ---------------- row-range allocation (warp-aggregated bump alloc) + dis ----------------
__global__ void k_offsets(int n) {
    int i = blockIdx.x * blockDim.x + threadIdx.x;
    int lane = threadIdx.x & 31;
    int c = (i < n) ? g_cnt[i] : 0;
    int s = c;
#pragma unroll
    for (int off = 1; off < 32; off <<= 1) {
        int v = __shfl_up_sync(0xffffffffu, s, off);
        if (lane >= off) s += v;
    }
    int warpTotal = __shfl_sync(0xffffffffu, s, 31);
    int base = 0;
    if (lane == 31) base = atomicAdd(&g_total, warpTotal);
    base = __shfl_sync(0xffffffffu, base, 31);
    if (i < n) {
        int rs = base + s - c;
        g_rowstart[i] = rs;
        g_cursor[i]   = rs;
        g_dis[i] = rsqrtf((float)(c + 1));
    }
}

// ---------------- CSR fill (2 edges/thread for atomic MLP) ----------------
__global__ void k_fill(const int* __restrict__ ei, int e) {
    int i = blockIdx.x * blockDim.x + threadIdx.x;
    int base = i << 1;
    if (base + 1 < e) {
        int2 s2 = *(const int2*)(ei + base);
        int2 d2 = *(const int2*)(ei + e + base);
        int p0 = atomicAdd(&g_cursor[d2.x], 1);
        int p1 = atomicAdd(&g_cursor[d2.y], 1);
        g_csrc[p0] = s2.x;
        g_csrc[p1] = s2.y;
    } else if (base < e) {
        int d = ei[e + base];
        int pos = atomicAdd(&g_cursor[d], 1);
        g_csrc[pos] = ei[base];
    }
}

// ---------------- GEMM h = x@W (FFMA2), writes fp32 h + fp16 hh ----------------
__global__ __launch_bounds__(128, 6) void k_gemm(const float* __restrict__ x,
                                                 const float* __restrict__ W,
                                                 int n) {
    __shared__ float xs[D][34];          // [k][row]
    int row0 = blockIdx.x * 32;

#pragma unroll
    for (int it = 0; it < 8; it++) {
        int i = it * 128 + threadIdx.x;
        int r = i >> 5;
        int q = i & 31;
        int gr = row0 + r;
        float4 v = make_float4(0.f, 0.f, 0.f, 0.f);
        if (gr < n) v = *(const float4*)(x + (size_t)gr * D + (q << 2));
        xs[q * 4 + 0][r] = v.x;
        xs[q * 4 + 1][r] = v.y;
        xs[q * 4 + 2][r] = v.z;
        xs[q * 4 + 3][r] = v.w;
    }
    __syncthreads();

    int warp = threadIdx.x >> 5;
    int lane = threadIdx.x & 31;
    int c = lane << 2;

    u64 acc[4][4];
#pragma unroll
    for (int rp = 0; rp < 4; rp++)
#pragma unroll
        for (int cc = 0; cc < 4; cc++) acc[rp][cc] = 0ULL;

#pragma unroll 4
    for (int k = 0; k < D; k++) {
        float4 wv = *(const float4*)(W + k * D + c);   // L1-resident
        u64 wd0 = pack2(wv.x), wd1 = pack2(wv.y), wd2 = pack2(wv.z), wd3 = pack2(wv.w);
        const u64* xp = (const u64*)&xs[k][warp * 8];  // 4 row-pairs (LDS.64)
        u64 x0 = xp[0], x1 = xp[1], x2 = xp[2], x3 = xp[3];
        fma2(acc[0][0], x0, wd0); fma2(acc[0][1], x0, wd1); fma2(acc[0][2], x0, wd2); fma2(acc[0][3], x0, wd3);
        fma2(acc[1][0], x1, wd0); fma2(acc[1][1], x1, wd1); fma2(acc[1][2], x1, wd2); fma2(acc[1][3], x1, wd3);
        fma2(acc[2][0], x2, wd0); fma2(acc[2][1], x2, wd1); fma2(acc[2][2], x2, wd2); fma2(acc[2][3], x2, wd3);
        fma2(acc[3][0], x3, wd0); fma2(acc[3][1], x3, wd1); fma2(acc[3][2], x3, wd2); fma2(acc[3][3], x3, wd3);
    }

#pragma unroll
    for (int rp = 0; rp < 4; rp++) {
        int gr0 = row0 + warp * 8 + rp * 2;
        float2 v0 = unpack2(acc[rp][0]);
        float2 v1 = unpack2(acc[rp][1]);
        float2 v2 = unpack2(acc[rp][2]);
        float2 v3 = unpack2(acc[rp][3]);
        float4 rA = make_float4(v0.x, v1.x, v2.x, v3.x);   // row gr0
        float4 rB = make_float4(v0.y, v1.y, v2.y, v3.y);   // row gr0+1
#pragma unroll
        for (int h2 = 0; h2 < 2; h2++) {
            int gr = gr0 + h2;
            if (gr < n) {
                float4 hv = h2 ? rB : rA;
                *(float4*)(g_h + (size_t)gr * D + c) = hv;
                __half2 p0 = __floats2half2_rn(hv.x, hv.y);
                __half2 p1 = __floats2half2_rn(hv.z, hv.w);
                *(__half2*)(g_hh + (size_t)gr * (D/2) + (lane << 1))     = p0;
                *(__half2*)(g_hh + (size_t)gr * (D/2) + (lane << 1) + 1) = p1;
            }
        }
    }
}

// ---------------- gather: warp per dst, fp16 payload, fp32 accumulation ----------------
// out[w] = (sum_{s in N(w)} hh[s]*dis[s] + h[w]*dis[w]) * dis[w] + b
__global__ __launch_bounds__(256) void k_gather(const float* __restrict__ b,
                                                float* __restrict__ out, int n) {
    int w = (blockIdx.x * blockDim.x + threadIdx.x) >> 5;
    int lane = threadIdx.x & 31;
    if (w >= n) return;
    int cnt = g_cnt[w];
    int start = g_rowstart[w];
    float nd = g_dis[w];
    int c = lane << 2;

    // self-loop term from fp32 h
    float4 hw = *(const float4*)(g_h + (size_t)w * D + c);
    float4 acc;
    acc.x = hw.x * nd; acc.y = hw.y * nd; acc.z = hw.z * nd; acc.w = hw.w * nd;

    int j = 0;
    while (j < cnt) {
        int batch = min(cnt - j, 32);
        int s = 0; float ds = 0.f;
        if (lane < batch) {
            s = g_csrc[start + j + lane];
            ds = g_dis[s];
        }
#pragma unroll 4
        for (int t = 0; t < batch; t++) {
            int st = __shfl_sync(0xffffffffu, s, t);
            float dt = __shfl_sync(0xffffffffu, ds, t);
            const __half2* hp = g_hh + (size_t)st * (D/2) + (lane << 1);
            uint2 raw = *(const uint2*)hp;            // 8B per lane
            __half2 a2 = *(const __half2*)&raw.x;
            __half2 b2 = *(const __half2*)&raw.y;
            float2 f0 = __half22float2(a2);
            float2 f1 = __half22float2(b2);
            acc.x = fmaf(f0.x, dt, acc.x);
            acc.y = fmaf(f0.y, dt, acc.y);
            acc.z = fmaf(f1.x, dt, acc.z);
            acc.w = fmaf(f1.y, dt, acc.w);
        }
        j += batch;
    }
    float4 bv = *(const float4*)(b + c);
    float4 o;
    o.x = acc.x * nd + bv.x;
    o.y = acc.y * nd + bv.y;
    o.z = acc.z * nd + bv.z;
    o.w = acc.w * nd + bv.w;
    *(float4*)(out + (size_t)w * D + c) = o;
}

extern "C" void kernel_launch(void* const* d_in, const int* in_sizes, int n_in,
                              void* d_out, int out_size) {
    const float* x  = (const float*)d_in[0];
    const int*   ei = (const int*)d_in[1];     // edge_index int32
    const float* W  = (const float*)d_in[2];
    const float* b  = (const float*)d_in[3];
    float* out = (float*)d_out;

    int n = in_sizes[0] / D;
    int e = in_sizes[1] / 2;

    // fork: GEMM on side stream, CSR build on main (capture) stream
    cudaEventRecord(g_fork.ev_fork, 0);
    cudaStreamWaitEvent(g_fork.s2, g_fork.ev_fork, 0);
    k_gemm<<<(n + 31) / 32, 128, 0, g_fork.s2>>>(x, W, n);

    k_cnt_init<<<(n + 255) / 256, 256>>>(n);
    k_cnt_count<<<(e / 4 + 256) / 256, 256>>>(ei, e);
    k_offsets<<<(n + 255) / 256, 256>>>(n);
    k_fill<<<(e / 2 + 256) / 256, 256>>>(ei, e);

    // join
    cudaEventRecord(g_fork.ev_join, g_fork.s2);
    cudaStreamWaitEvent(0, g_fork.ev_join, 0);

    k_gather<<<(n * 32 + 255) / 256, 256>>>(b, out, n);
}

// round 10
// speedup vs baseline: 2.4921x; 1.1985x over previous
#include <cuda_runtime.h>
#include <cuda_fp16.h>
#include <mma.h>
#include <stdint.h>

using namespace nvcuda;

#define D 128
#define MAX_N 50048
#define MAX_E 600064

#define XW_LD 136                               // half elements per row (pad)
#define SMEM_GEMM_TOTAL (2 * 128 * XW_LD * 2)   // 69632 B (xh + wh; C reuses xh)

// Scratch (device globals — no allocation). All fully rewritten each launch.
__device__ float   g_h[(size_t)MAX_N * D];      // h = x@W (fp32)
__device__ __half2 g_hh[(size_t)MAX_N * (D/2)]; // h in fp16 (gather payload)
__device__ float   g_dis[MAX_N];
__device__ int     g_cnt[MAX_N];
__device__ int     g_rowstart[MAX_N];
__device__ int     g_cursor[MAX_N];
__device__ int     g_csrc[MAX_E];
__device__ int     g_total;

// ---- streams/events + smem attr (program-load init; capture-safe) ----
__global__ void k_gemm_wmma(const float* __restrict__ x, const float* __restrict__ W, int n);
struct ForkCtx {
    cudaStream_t s2;
    cudaEvent_t ev_fork, ev_join;
    ForkCtx() {
        cudaStreamCreateWithFlags(&s2, cudaStreamNonBlocking);
        cudaEventCreateWithFlags(&ev_fork, cudaEventDisableTiming);
        cudaEventCreateWithFlags(&ev_join, cudaEventDisableTiming);
        cudaFuncSetAttribute(k_gemm_wmma, cudaFuncAttributeMaxDynamicSharedMemorySize,
                             SMEM_GEMM_TOTAL);
    }
};
static ForkCtx g_fork;

// ---------------- degree count ----------------
__global__ void k_cnt_init(int n) {
    int i = blockIdx.x * blockDim.x + threadIdx.x;
    if (i < n) g_cnt[i] = 0;
    if (i == 0) g_total = 0;
}
__global__ void k_cnt_count(const int* __restrict__ ei, int e) {
    int i = blockIdx.x * blockDim.x + threadIdx.x;
    int base = i << 2;
    if (base + 3 < e) {
        int4 d4 = *(const int4*)(ei + e + base);
        atomicAdd(&g_cnt[d4.x], 1);
        atomicAdd(&g_cnt[d4.y], 1);
        atomicAdd(&g_cnt[d4.z], 1);
        atomicAdd(&g_cnt[d4.w], 1);
    } else {
        for (int j = base; j < e; j++) atomicAdd(&g_cnt[ei[e + j]], 1);
    }
}

// ---------------- row-range allocation (warp-aggregated bump alloc) + dis ----------------
__global__ void k_offsets(int n) {
    int i = blockIdx.x * blockDim.x + threadIdx.x;
    int lane = threadIdx.x & 31;
    int c = (i < n) ? g_cnt[i] : 0;
    int s = c;
#pragma unroll
    for (int off = 1; off < 32; off <<= 1) {
        int v = __shfl_up_sync(0xffffffffu, s, off);
        if (lane >= off) s += v;
    }
    int warpTotal = __shfl_sync(0xffffffffu, s, 31);
    int base = 0;
    if (lane == 31) base = atomicAdd(&g_total, warpTotal);
    base = __shfl_sync(0xffffffffu, base, 31);
    if (i < n) {
        int rs = base + s - c;
        g_rowstart[i] = rs;
        g_cursor[i]   = rs;
        g_dis[i] = rsqrtf((float)(c + 1));
    }
}

// ---------------- CSR fill (4 edges/thread for atomic MLP) ----------------
__global__ void k_fill(const int* __restrict__ ei, int e) {
    int i = blockIdx.x * blockDim.x + threadIdx.x;
    int base = i << 2;
    if (base + 3 < e) {
        int4 s4 = *(const int4*)(ei + base);
        int4 d4 = *(const int4*)(ei + e + base);
        int p0 = atomicAdd(&g_cursor[d4.x], 1);
        int p1 = atomicAdd(&g_cursor[d4.y], 1);
        int p2 = atomicAdd(&g_cursor[d4.z], 1);
        int p3 = atomicAdd(&g_cursor[d4.w], 1);
        g_csrc[p0] = s4.x;
        g_csrc[p1] = s4.y;
        g_csrc[p2] = s4.z;
        g_csrc[p3] = s4.w;
    } else {
        for (int j = base; j < e; j++) {
            int d = ei[e + j];
            int pos = atomicAdd(&g_cursor[d], 1);
            g_csrc[pos] = ei[j];
        }
    }
}

// ---------------- GEMM h = x@W via wmma (HMMA fp16 in, fp32 acc) ----------------
// 256 thr, tile M=128 N=128 K=128. x,W staged to smem as fp16 (converted in-flight).
// 8 warps: warp (wm = wid&3, wn = wid>>2) computes rows wm*32..+31, cols wn*64..+63
// = 2x4 wmma 16x16x16 accumulators. C staged through smem for vectorized epilogue.
__global__ __launch_bounds__(256) void k_gemm_wmma(const float* __restrict__ x,
                                                   const float* __restrict__ W, int n) {
    extern __shared__ char smem[];
    __half* xh = (__half*)smem;                          // [128][XW_LD]
    __half* wh = (__half*)(smem + 128 * XW_LD * 2);      // [128][XW_LD]
    float*  cs = (float*)smem;                           // reuse for C [128][128]
    int tid = threadIdx.x;
    int row0 = blockIdx.x * 128;

    // stage x (convert f32->f16)
#pragma unroll
    for (int it = 0; it < 16; it++) {
        int idx = it * 256 + tid;            // 4096 float4s
        int r = idx >> 5;
        int q = idx & 31;
        int gr = row0 + r;
        float4 v = make_float4(0.f, 0.f, 0.f, 0.f);
        if (gr < n) v = *(const float4*)(x + (size_t)gr * D + (q << 2));
        __half2* p = (__half2*)(xh + r * XW_LD + (q << 2));
        p[0] = __floats2half2_rn(v.x, v.y);
        p[1] = __floats2half2_rn(v.z, v.w);
    }
    // stage W (convert f32->f16); W[k][n] row-major == wmma matrix_b row_major
#pragma unroll
    for (int it = 0; it < 16; it++) {
        int idx = it * 256 + tid;
        int r = idx >> 5;
        int q = idx & 31;
        float4 v = *(const float4*)(W + r * D + (q << 2));
        __half2* p = (__half2*)(wh + r * XW_LD + (q << 2));
        p[0] = __floats2half2_rn(v.x, v.y);
        p[1] = __floats2half2_rn(v.z, v.w);
    }
    __syncthreads();

    int wid = tid >> 5;
    int wm = wid & 3;           // row strip 0..3 (32 rows each)
    int wn = wid >> 2;          // col half 0..1 (64 cols each)

    wmma::fragment<wmma::accumulator, 16, 16, 16, float> c[2][4];
#pragma unroll
    for (int i = 0; i < 2; i++)
#pragma unroll
        for (int j = 0; j < 4; j++) wmma::fill_fragment(c[i][j], 0.0f);

#pragma unroll
    for (int k = 0; k < 8; k++) {
        wmma::fragment<wmma::matrix_a, 16, 16, 16, __half, wmma::row_major> a[2];
        wmma::fragment<wmma::matrix_b, 16, 16, 16, __half, wmma::row_major> bf[4];
#pragma unroll
        for (int i = 0; i < 2; i++)
            wmma::load_matrix_sync(a[i], xh + (wm * 32 + i * 16) * XW_LD + k * 16, XW_LD);
#pragma unroll
        for (int j = 0; j < 4; j++)
            wmma::load_matrix_sync(bf[j], wh + (k * 16) * XW_LD + wn * 64 + j * 16, XW_LD);
#pragma unroll
        for (int i = 0; i < 2; i++)
#pragma unroll
            for (int j = 0; j < 4; j++)
                wmma::mma_sync(c[i][j], a[i], bf[j], c[i][j]);
    }

    __syncthreads();            // done with xh/wh; reuse as C
#pragma unroll
    for (int i = 0; i < 2; i++)
#pragma unroll
        for (int j = 0; j < 4; j++)
            wmma::store_matrix_sync(cs + (wm * 32 + i * 16) * 128 + wn * 64 + j * 16,
                                    c[i][j], 128, wmma::mem_row_major);
    __syncthreads();

    // epilogue: write h (f32) + hh (fp16)
#pragma unroll
    for (int it = 0; it < 16; it++) {
        int idx = it * 256 + tid;
        int r = idx >> 5;
        int q = idx & 31;
        int gr = row0 + r;
        if (gr < n) {
            float4 v = *(const float4*)(cs + r * 128 + (q << 2));
            *(float4*)(g_h + (size_t)gr * D + (q << 2)) = v;
            __half2* hp = (__half2*)(g_hh + (size_t)gr * (D / 2) + (q << 1));
            hp[0] = __floats2half2_rn(v.x, v.y);
            hp[1] = __floats2half2_rn(v.z, v.w);
        }
    }
}

// ---------------- gather: warp per dst, fp16 payload, fp32 accumulation ----------------
__global__ __launch_bounds__(256) void k_gather(const float* __restrict__ b,
                                                float* __restrict__ out, int n) {
    int w = (blockIdx.x * blockDim.x + threadIdx.x) >> 5;
    int lane = threadIdx.x & 31;
    if (w >= n) return;
    int cnt = g_cnt[w];
    int start = g_rowstart[w];
    float nd = g_dis[w];
    int c = lane << 2;

    float4 hw = *(const float4*)(g_h + (size_t)w * D + c);
    float4 acc;
    acc.x = hw.x * nd; acc.y = hw.y * nd; acc.z = hw.z * nd; acc.w = hw.w * nd;

    int j = 0;
    while (j < cnt) {
        int batch = min(cnt - j, 32);
        int s = 0; float ds = 0.f;
        if (lane < batch) {
            s = g_csrc[start + j + lane];
            ds = g_dis[s];
        }
#pragma unroll 8
        for (int t = 0; t < batch; t++) {
            int st = __shfl_sync(0xffffffffu, s, t);
            float dt = __shfl_sync(0xffffffffu, ds, t);
            const __half2* hp = g_hh + (size_t)st * (D / 2) + (lane << 1);
            uint2 raw = *(const uint2*)hp;
            __half2 a2 = *(const __half2*)&raw.x;
            __half2 b2 = *(const __half2*)&raw.y;
            float2 f0 = __half22float2(a2);
            float2 f1 = __half22float2(b2);
            acc.x = fmaf(f0.x, dt, acc.x);
            acc.y = fmaf(f0.y, dt, acc.y);
            acc.z = fmaf(f1.x, dt, acc.z);
            acc.w = fmaf(f1.y, dt, acc.w);
        }
        j += batch;
    }
    float4 bv = *(const float4*)(b + c);
    float4 o;
    o.x = acc.x * nd + bv.x;
    o.y = acc.y * nd + bv.y;
    o.z = acc.z * nd + bv.z;
    o.w = acc.w * nd + bv.w;
    *(float4*)(out + (size_t)w * D + c) = o;
}

extern "C" void kernel_launch(void* const* d_in, const int* in_sizes, int n_in,
                              void* d_out, int out_size) {
    const float* x  = (const float*)d_in[0];
    const int*   ei = (const int*)d_in[1];     // edge_index int32
    const float* W  = (const float*)d_in[2];
    const float* b  = (const float*)d_in[3];
    float* out = (float*)d_out;

    int n = in_sizes[0] / D;
    int e = in_sizes[1] / 2;

    // fork: wmma GEMM on side stream, CSR build on main stream
    cudaEventRecord(g_fork.ev_fork, 0);
    cudaStreamWaitEvent(g_fork.s2, g_fork.ev_fork, 0);
    k_gemm_wmma<<<(n + 127) / 128, 256, SMEM_GEMM_TOTAL, g_fork.s2>>>(x, W, n);

    k_cnt_init<<<(n + 255) / 256, 256>>>(n);
    k_cnt_count<<<(e / 4 + 256) / 256, 256>>>(ei, e);
    k_offsets<<<(n + 255) / 256, 256>>>(n);
    k_fill<<<(e / 4 + 256) / 256, 256>>>(ei, e);

    // join
    cudaEventRecord(g_fork.ev_join, g_fork.s2);
    cudaStreamWaitEvent(0, g_fork.ev_join, 0);

    k_gather<<<(n * 32 + 255) / 256, 256>>>(b, out, n);
}

// round 11
// speedup vs baseline: 2.6294x; 1.0551x over previous
#include <cuda_runtime.h>
#include <cuda_fp16.h>
#include <mma.h>
#include <stdint.h>

using namespace nvcuda;

#define D 128
#define MAX_N 50048
#define MAX_E 600064

#define XW_LD 136
#define SMEM_GEMM_TOTAL (2 * 128 * XW_LD * 2)   // 69632 B (xh + wh; C reuses)

// Scratch (device globals — no allocation). Self-cleaning: g_cnt/g_total are
// zero at entry of every launch (zero-init at load; k_gather re-zeroes).
__device__ __half2 g_hh[(size_t)MAX_N * (D/2)]; // h = x@W in fp16
__device__ float   g_dis[MAX_N];
__device__ int     g_cnt[MAX_N];
__device__ int     g_rowstart[MAX_N];
__device__ int     g_cursor[MAX_N];
__device__ int     g_csrc[MAX_E];
__device__ int     g_total;

// ---- streams/events + smem attr (program-load init; capture-safe) ----
__global__ void k_gemm_wmma(const float* __restrict__ x, const float* __restrict__ W, int n);
struct ForkCtx {
    cudaStream_t s2, s3;
    cudaEvent_t ev_fork, ev_gemm, ev_cnt, ev_off, ev_fill;
    ForkCtx() {
        cudaStreamCreateWithFlags(&s2, cudaStreamNonBlocking);
        cudaStreamCreateWithFlags(&s3, cudaStreamNonBlocking);
        cudaEventCreateWithFlags(&ev_fork, cudaEventDisableTiming);
        cudaEventCreateWithFlags(&ev_gemm, cudaEventDisableTiming);
        cudaEventCreateWithFlags(&ev_cnt,  cudaEventDisableTiming);
        cudaEventCreateWithFlags(&ev_off,  cudaEventDisableTiming);
        cudaEventCreateWithFlags(&ev_fill, cudaEventDisableTiming);
        cudaFuncSetAttribute(k_gemm_wmma, cudaFuncAttributeMaxDynamicSharedMemorySize,
                             SMEM_GEMM_TOTAL);
    }
};
static ForkCtx g_fork;

// ---------------- degree count over edge range [start, start+cnt) ----------------
__global__ void k_cnt_count(const int* __restrict__ ei, int e, int start, int cnt) {
    int i = blockIdx.x * blockDim.x + threadIdx.x;
    int base = start + (i << 2);
    if ((i << 2) + 3 < cnt) {
        int4 d4 = *(const int4*)(ei + e + base);
        atomicAdd(&g_cnt[d4.x], 1);
        atomicAdd(&g_cnt[d4.y], 1);
        atomicAdd(&g_cnt[d4.z], 1);
        atomicAdd(&g_cnt[d4.w], 1);
    } else {
        for (int j = base; j < start + cnt; j++) atomicAdd(&g_cnt[ei[e + j]], 1);
    }
}

// ---------------- row-range allocation (block-aggregated bump alloc) + dis ----------------
__global__ void k_offsets(int n) {
    __shared__ int wsum[8];
    __shared__ int bbase;
    int tid = threadIdx.x;
    int i = blockIdx.x * 256 + tid;
    int lane = tid & 31;
    int wid = tid >> 5;
    int c = (i < n) ? g_cnt[i] : 0;
    int s = c;
#pragma unroll
    for (int off = 1; off < 32; off <<= 1) {
        int v = __shfl_up_sync(0xffffffffu, s, off);
        if (lane >= off) s += v;
    }
    if (lane == 31) wsum[wid] = s;
    __syncthreads();
    if (tid == 0) {
        int t = 0;
#pragma unroll
        for (int w = 0; w < 8; w++) { int v = wsum[w]; wsum[w] = t; t += v; }
        bbase = atomicAdd(&g_total, t);
    }
    __syncthreads();
    if (i < n) {
        int rs = bbase + wsum[wid] + s - c;     // exclusive prefix
        g_rowstart[i] = rs;
        g_cursor[i]   = rs;
        g_dis[i] = rsqrtf((float)(c + 1));      // +1 self-loop
    }
}

// ---------------- CSR fill over edge range (4 edges/thread) ----------------
__global__ void k_fill(const int* __restrict__ ei, int e, int start, int cnt) {
    int i = blockIdx.x * blockDim.x + threadIdx.x;
    int base = start + (i << 2);
    if ((i << 2) + 3 < cnt) {
        int4 s4 = *(const int4*)(ei + base);
        int4 d4 = *(const int4*)(ei + e + base);
        int p0 = atomicAdd(&g_cursor[d4.x], 1);
        int p1 = atomicAdd(&g_cursor[d4.y], 1);
        int p2 = atomicAdd(&g_cursor[d4.z], 1);
        int p3 = atomicAdd(&g_cursor[d4.w], 1);
        g_csrc[p0] = s4.x;
        g_csrc[p1] = s4.y;
        g_csrc[p2] = s4.z;
        g_csrc[p3] = s4.w;
    } else {
        for (int j = base; j < start + cnt; j++) {
            int d = ei[e + j];
            int pos = atomicAdd(&g_cursor[d], 1);
            g_csrc[pos] = ei[j];
        }
    }
}

// ---------------- GEMM h = x@W via wmma (HMMA fp16 in, fp32 acc) ----------------
__global__ __launch_bounds__(256) void k_gemm_wmma(const float* __restrict__ x,
                                                   const float* __restrict__ W, int n) {
    extern __shared__ char smem[];
    __half* xh = (__half*)smem;                          // [128][XW_LD]
    __half* wh = (__half*)(smem + 128 * XW_LD * 2);      // [128][XW_LD]
    float*  cs = (float*)smem;                           // reuse for C [128][128]
    int tid = threadIdx.x;
    int row0 = blockIdx.x * 128;

#pragma unroll
    for (int it = 0; it < 16; it++) {
        int idx = it * 256 + tid;
        int r = idx >> 5;
        int q = idx & 31;
        int gr = row0 + r;
        float4 v = make_float4(0.f, 0.f, 0.f, 0.f);
        if (gr < n) v = *(const float4*)(x + (size_t)gr * D + (q << 2));
        __half2* p = (__half2*)(xh + r * XW_LD + (q << 2));
        p[0] = __floats2half2_rn(v.x, v.y);
        p[1] = __floats2half2_rn(v.z, v.w);
    }
#pragma unroll
    for (int it = 0; it < 16; it++) {
        int idx = it * 256 + tid;
        int r = idx >> 5;
        int q = idx & 31;
        float4 v = *(const float4*)(W + r * D + (q << 2));
        __half2* p = (__half2*)(wh + r * XW_LD + (q << 2));
        p[0] = __floats2half2_rn(v.x, v.y);
        p[1] = __floats2half2_rn(v.z, v.w);
    }
    __syncthreads();

    int wid = tid >> 5;
    int wm = wid & 3;
    int wn = wid >> 2;

    wmma::fragment<wmma::accumulator, 16, 16, 16, float> c[2][4];
#pragma unroll
    for (int i = 0; i < 2; i++)
#pragma unroll
        for (int j = 0; j < 4; j++) wmma::fill_fragment(c[i][j], 0.0f);

#pragma unroll
    for (int k = 0; k < 8; k++) {
        wmma::fragment<wmma::matrix_a, 16, 16, 16, __half, wmma::row_major> a[2];
        wmma::fragment<wmma::matrix_b, 16, 16, 16, __half, wmma::row_major> bf[4];
#pragma unroll
        for (int i = 0; i < 2; i++)
            wmma::load_matrix_sync(a[i], xh + (wm * 32 + i * 16) * XW_LD + k * 16, XW_LD);
#pragma unroll
        for (int j = 0; j < 4; j++)
            wmma::load_matrix_sync(bf[j], wh + (k * 16) * XW_LD + wn * 64 + j * 16, XW_LD);
#pragma unroll
        for (int i = 0; i < 2; i++)
#pragma unroll
            for (int j = 0; j < 4; j++)
                wmma::mma_sync(c[i][j], a[i], bf[j], c[i][j]);
    }

    __syncthreads();
#pragma unroll
    for (int i = 0; i < 2; i++)
#pragma unroll
        for (int j = 0; j < 4; j++)
            wmma::store_matrix_sync(cs + (wm * 32 + i * 16) * 128 + wn * 64 + j * 16,
                                    c[i][j], 128, wmma::mem_row_major);
    __syncthreads();

    // epilogue: write hh (fp16 only)
#pragma unroll
    for (int it = 0; it < 16; it++) {
        int idx = it * 256 + tid;
        int r = idx >> 5;
        int q = idx & 31;
        int gr = row0 + r;
        if (gr < n) {
            float4 v = *(const float4*)(cs + r * 128 + (q << 2));
            __half2* hp = (__half2*)(g_hh + (size_t)gr * (D / 2) + (q << 1));
            hp[0] = __floats2half2_rn(v.x, v.y);
            hp[1] = __floats2half2_rn(v.z, v.w);
        }
    }
}

// ---------------- gather: warp per dst; fp16 payload; self-cleans g_cnt ----------------
// out[w] = (sum_{s in N(w)} hh[s]*dis[s] + hh[w]*dis[w]) * dis[w] + b
__global__ __launch_bounds__(256) void k_gather(const float* __restrict__ b,
                                                float* __restrict__ out, int n) {
    int w = (blockIdx.x * blockDim.x + threadIdx.x) >> 5;
    int lane = threadIdx.x & 31;
    if (w >= n) return;
    int cnt = g_cnt[w];
    int start = g_rowstart[w];
    float nd = g_dis[w];

    // self-loop term (fp16 payload)
    float4 acc;
    {
        uint2 raw = *(const uint2*)(g_hh + (size_t)w * (D / 2) + (lane << 1));
        float2 f0 = __half22float2(*(const __half2*)&raw.x);
        float2 f1 = __half22float2(*(const __half2*)&raw.y);
        acc.x = f0.x * nd; acc.y = f0.y * nd; acc.z = f1.x * nd; acc.w = f1.y * nd;
    }

    int j = 0;
    while (j < cnt) {
        int batch = min(cnt - j, 32);
        int s = 0; float ds = 0.f;
        if (lane < batch) {
            s = g_csrc[start + j + lane];
            ds = g_dis[s];
        }
#pragma unroll 8
        for (int t = 0; t < batch; t++) {
            int st = __shfl_sync(0xffffffffu, s, t);
            float dt = __shfl_sync(0xffffffffu, ds, t);
            uint2 raw = *(const uint2*)(g_hh + (size_t)st * (D / 2) + (lane << 1));
            float2 f0 = __half22float2(*(const __half2*)&raw.x);
            float2 f1 = __half22float2(*(const __half2*)&raw.y);
            acc.x = fmaf(f0.x, dt, acc.x);
            acc.y = fmaf(f0.y, dt, acc.y);
            acc.z = fmaf(f1.x, dt, acc.z);
            acc.w = fmaf(f1.y, dt, acc.w);
        }
        j += batch;
    }
    int c = lane << 2;
    float4 bv = *(const float4*)(b + c);
    float4 o;
    o.x = acc.x * nd + bv.x;
    o.y = acc.y * nd + bv.y;
    o.z = acc.z * nd + bv.z;
    o.w = acc.w * nd + bv.w;
    *(float4*)(out + (size_t)w * D + c) = o;

    // self-clean for next launch (graph replay determinism)
    if (lane == 0) g_cnt[w] = 0;
    if (w == 0 && lane == 1) g_total = 0;
}

extern "C" void kernel_launch(void* const* d_in, const int* in_sizes, int n_in,
                              void* d_out, int out_size) {
    const float* x  = (const float*)d_in[0];
    const int*   ei = (const int*)d_in[1];     // edge_index int32
    const float* W  = (const float*)d_in[2];
    const float* b  = (const float*)d_in[3];
    float* out = (float*)d_out;

    int n = in_sizes[0] / D;
    int e = in_sizes[1] / 2;
    int half = (e / 2) & ~3;                   // 16B-aligned split
    int rest = e - half;

    ForkCtx& F = g_fork;

    // fork from main
    cudaEventRecord(F.ev_fork, 0);
    cudaStreamWaitEvent(F.s2, F.ev_fork, 0);
    cudaStreamWaitEvent(F.s3, F.ev_fork, 0);

    // s2: GEMM (off critical path)
    k_gemm_wmma<<<(n + 127) / 128, 256, SMEM_GEMM_TOTAL, F.s2>>>(x, W, n);
    cudaEventRecord(F.ev_gemm, F.s2);

    // count split across main + s3
    k_cnt_count<<<(half / 4 + 255) / 256, 256, 0, 0>>>(ei, e, 0, half);
    k_cnt_count<<<(rest / 4 + 256) / 256, 256, 0, F.s3>>>(ei, e, half, rest);
    cudaEventRecord(F.ev_cnt, F.s3);
    cudaStreamWaitEvent(0, F.ev_cnt, 0);

    // offsets on main
    k_offsets<<<(n + 255) / 256, 256, 0, 0>>>(n);
    cudaEventRecord(F.ev_off, 0);
    cudaStreamWaitEvent(F.s3, F.ev_off, 0);

    // fill split across main + s3
    k_fill<<<(half / 4 + 255) / 256, 256, 0, 0>>>(ei, e, 0, half);
    k_fill<<<(rest / 4 + 256) / 256, 256, 0, F.s3>>>(ei, e, half, rest);
    cudaEventRecord(F.ev_fill, F.s3);

    // join: gather needs fill (both halves) + gemm
    cudaStreamWaitEvent(0, F.ev_fill, 0);
    cudaStreamWaitEvent(0, F.ev_gemm, 0);
    k_gather<<<(n * 32 + 255) / 256, 256, 0, 0>>>(b, out, n);
}

// round 12
// speedup vs baseline: 2.9192x; 1.1102x over previous
#include <cuda_runtime.h>
#include <cuda_fp16.h>
#include <mma.h>
#include <stdint.h>

using namespace nvcuda;

#define D 128
#define MAX_N 50048
#define BKT_CAP 128                             // max in-degree capacity (Poisson(12) tail ~1e-60)

#define XW_LD 136
#define SMEM_GEMM_TOTAL (2 * 128 * XW_LD * 2)   // 69632 B (xh + wh; C reuses)

// Scratch (device globals — no allocation). Self-cleaning: g_cnt is zero at
// entry of every launch (zero-init at load; k_gather re-zeroes own row).
__device__ __half2 g_hh[(size_t)MAX_N * (D/2)]; // h = x@W in fp16
__device__ float   g_dis[MAX_N];
__device__ int     g_cnt[MAX_N];
__device__ int     g_bkt[(size_t)MAX_N * BKT_CAP]; // bucketed src ids per dst

// ---- streams/events + smem attr (program-load init; capture-safe) ----
__global__ void k_gemm_wmma(const float* __restrict__ x, const float* __restrict__ W, int n);
struct ForkCtx {
    cudaStream_t s2, s3;
    cudaEvent_t ev_fork, ev_gemm, ev_fill3;
    ForkCtx() {
        cudaStreamCreateWithFlags(&s2, cudaStreamNonBlocking);
        cudaStreamCreateWithFlags(&s3, cudaStreamNonBlocking);
        cudaEventCreateWithFlags(&ev_fork,  cudaEventDisableTiming);
        cudaEventCreateWithFlags(&ev_gemm,  cudaEventDisableTiming);
        cudaEventCreateWithFlags(&ev_fill3, cudaEventDisableTiming);
        cudaFuncSetAttribute(k_gemm_wmma, cudaFuncAttributeMaxDynamicSharedMemorySize,
                             SMEM_GEMM_TOTAL);
    }
};
static ForkCtx g_fork;

// ---------------- single-pass bucket fill (count + scatter fused) ----------------
// 4 edges/thread for atomic MLP. Range [start, start+cnt).
__global__ void k_fill(const int* __restrict__ ei, int e, int start, int cnt) {
    int i = blockIdx.x * blockDim.x + threadIdx.x;
    int base = start + (i << 2);
    if ((i << 2) + 3 < cnt) {
        int4 s4 = *(const int4*)(ei + base);
        int4 d4 = *(const int4*)(ei + e + base);
        int p0 = atomicAdd(&g_cnt[d4.x], 1);
        int p1 = atomicAdd(&g_cnt[d4.y], 1);
        int p2 = atomicAdd(&g_cnt[d4.z], 1);
        int p3 = atomicAdd(&g_cnt[d4.w], 1);
        g_bkt[(size_t)d4.x * BKT_CAP + p0] = s4.x;
        g_bkt[(size_t)d4.y * BKT_CAP + p1] = s4.y;
        g_bkt[(size_t)d4.z * BKT_CAP + p2] = s4.z;
        g_bkt[(size_t)d4.w * BKT_CAP + p3] = s4.w;
    } else {
        for (int j = base; j < start + cnt; j++) {
            int d = ei[e + j];
            int pos = atomicAdd(&g_cnt[d], 1);
            g_bkt[(size_t)d * BKT_CAP + pos] = ei[j];
        }
    }
}

// ---------------- dis = rsqrt(deg+1) ----------------
__global__ void k_dis(int n) {
    int i = blockIdx.x * blockDim.x + threadIdx.x;
    if (i < n) g_dis[i] = rsqrtf((float)(g_cnt[i] + 1));
}

// ---------------- GEMM h = x@W via wmma (HMMA fp16 in, fp32 acc) ----------------
__global__ __launch_bounds__(256) void k_gemm_wmma(const float* __restrict__ x,
                                                   const float* __restrict__ W, int n) {
    extern __shared__ char smem[];
    __half* xh = (__half*)smem;                          // [128][XW_LD]
    __half* wh = (__half*)(smem + 128 * XW_LD * 2);      // [128][XW_LD]
    float*  cs = (float*)smem;                           // reuse for C [128][128]
    int tid = threadIdx.x;
    int row0 = blockIdx.x * 128;

#pragma unroll
    for (int it = 0; it < 16; it++) {
        int idx = it * 256 + tid;
        int r = idx >> 5;
        int q = idx & 31;
        int gr = row0 + r;
        float4 v = make_float4(0.f, 0.f, 0.f, 0.f);
        if (gr < n) v = *(const float4*)(x + (size_t)gr * D + (q << 2));
        __half2* p = (__half2*)(xh + r * XW_LD + (q << 2));
        p[0] = __floats2half2_rn(v.x, v.y);
        p[1] = __floats2half2_rn(v.z, v.w);
    }
#pragma unroll
    for (int it = 0; it < 16; it++) {
        int idx = it * 256 + tid;
        int r = idx >> 5;
        int q = idx & 31;
        float4 v = *(const float4*)(W + r * D + (q << 2));
        __half2* p = (__half2*)(wh + r * XW_LD + (q << 2));
        p[0] = __floats2half2_rn(v.x, v.y);
        p[1] = __floats2half2_rn(v.z, v.w);
    }
    __syncthreads();

    int wid = tid >> 5;
    int wm = wid & 3;
    int wn = wid >> 2;

    wmma::fragment<wmma::accumulator, 16, 16, 16, float> c[2][4];
#pragma unroll
    for (int i = 0; i < 2; i++)
#pragma unroll
        for (int j = 0; j < 4; j++) wmma::fill_fragment(c[i][j], 0.0f);

#pragma unroll
    for (int k = 0; k < 8; k++) {
        wmma::fragment<wmma::matrix_a, 16, 16, 16, __half, wmma::row_major> a[2];
        wmma::fragment<wmma::matrix_b, 16, 16, 16, __half, wmma::row_major> bf[4];
#pragma unroll
        for (int i = 0; i < 2; i++)
            wmma::load_matrix_sync(a[i], xh + (wm * 32 + i * 16) * XW_LD + k * 16, XW_LD);
#pragma unroll
        for (int j = 0; j < 4; j++)
            wmma::load_matrix_sync(bf[j], wh + (k * 16) * XW_LD + wn * 64 + j * 16, XW_LD);
#pragma unroll
        for (int i = 0; i < 2; i++)
#pragma unroll
            for (int j = 0; j < 4; j++)
                wmma::mma_sync(c[i][j], a[i], bf[j], c[i][j]);
    }

    __syncthreads();
#pragma unroll
    for (int i = 0; i < 2; i++)
#pragma unroll
        for (int j = 0; j < 4; j++)
            wmma::store_matrix_sync(cs + (wm * 32 + i * 16) * 128 + wn * 64 + j * 16,
                                    c[i][j], 128, wmma::mem_row_major);
    __syncthreads();

#pragma unroll
    for (int it = 0; it < 16; it++) {
        int idx = it * 256 + tid;
        int r = idx >> 5;
        int q = idx & 31;
        int gr = row0 + r;
        if (gr < n) {
            float4 v = *(const float4*)(cs + r * 128 + (q << 2));
            __half2* hp = (__half2*)(g_hh + (size_t)gr * (D / 2) + (q << 1));
            hp[0] = __floats2half2_rn(v.x, v.y);
            hp[1] = __floats2half2_rn(v.z, v.w);
        }
    }
}

// ---------------- gather: warp per dst; fp16 payload; self-cleans g_cnt ----------------
// out[w] = (sum_{s in bkt(w)} hh[s]*dis[s] + hh[w]*dis[w]) * dis[w] + b
__global__ __launch_bounds__(256) void k_gather(const float* __restrict__ b,
                                                float* __restrict__ out, int n) {
    int w = (blockIdx.x * blockDim.x + threadIdx.x) >> 5;
    int lane = threadIdx.x & 31;
    if (w >= n) return;
    int cnt = g_cnt[w];                          // own row — read before own reset
    float nd = g_dis[w];
    const int* brow = g_bkt + (size_t)w * BKT_CAP;

    // self-loop term (fp16 payload)
    float4 acc;
    {
        uint2 raw = *(const uint2*)(g_hh + (size_t)w * (D / 2) + (lane << 1));
        float2 f0 = __half22float2(*(const __half2*)&raw.x);
        float2 f1 = __half22float2(*(const __half2*)&raw.y);
        acc.x = f0.x * nd; acc.y = f0.y * nd; acc.z = f1.x * nd; acc.w = f1.y * nd;
    }

    int j = 0;
    while (j < cnt) {
        int batch = min(cnt - j, 32);
        int s = 0; float ds = 0.f;
        if (lane < batch) {
            s = brow[j + lane];
            ds = g_dis[s];                       // precomputed — no race with cnt reset
        }
#pragma unroll 8
        for (int t = 0; t < batch; t++) {
            int st = __shfl_sync(0xffffffffu, s, t);
            float dt = __shfl_sync(0xffffffffu, ds, t);
            uint2 raw = *(const uint2*)(g_hh + (size_t)st * (D / 2) + (lane << 1));
            float2 f0 = __half22float2(*(const __half2*)&raw.x);
            float2 f1 = __half22float2(*(const __half2*)&raw.y);
            acc.x = fmaf(f0.x, dt, acc.x);
            acc.y = fmaf(f0.y, dt, acc.y);
            acc.z = fmaf(f1.x, dt, acc.z);
            acc.w = fmaf(f1.y, dt, acc.w);
        }
        j += batch;
    }
    int c = lane << 2;
    float4 bv = *(const float4*)(b + c);
    float4 o;
    o.x = acc.x * nd + bv.x;
    o.y = acc.y * nd + bv.y;
    o.z = acc.z * nd + bv.z;
    o.w = acc.w * nd + bv.w;
    *(float4*)(out + (size_t)w * D + c) = o;

    // self-clean for next launch (own row only; ordered after own read)
    if (lane == 0) g_cnt[w] = 0;
}

extern "C" void kernel_launch(void* const* d_in, const int* in_sizes, int n_in,
                              void* d_out, int out_size) {
    const float* x  = (const float*)d_in[0];
    const int*   ei = (const int*)d_in[1];     // edge_index int32
    const float* W  = (const float*)d_in[2];
    const float* b  = (const float*)d_in[3];
    float* out = (float*)d_out;

    int n = in_sizes[0] / D;
    int e = in_sizes[1] / 2;
    int half = (e / 2) & ~3;                   // 16B-aligned split
    int rest = e - half;

    ForkCtx& F = g_fork;

    // fork
    cudaEventRecord(F.ev_fork, 0);
    cudaStreamWaitEvent(F.s2, F.ev_fork, 0);
    cudaStreamWaitEvent(F.s3, F.ev_fork, 0);

    // s2: GEMM (off critical path)
    k_gemm_wmma<<<(n + 127) / 128, 256, SMEM_GEMM_TOTAL, F.s2>>>(x, W, n);
    cudaEventRecord(F.ev_gemm, F.s2);

    // bucket fill split across main + s3 (count+scatter fused, single pass)
    k_fill<<<(half / 4 + 255) / 256, 256, 0, 0>>>(ei, e, 0, half);
    k_fill<<<(rest / 4 + 256) / 256, 256, 0, F.s3>>>(ei, e, half, rest);
    cudaEventRecord(F.ev_fill3, F.s3);
    cudaStreamWaitEvent(0, F.ev_fill3, 0);

    // dis (needs all counts)
    k_dis<<<(n + 255) / 256, 256, 0, 0>>>(n);

    // gather (needs dis + gemm)
    cudaStreamWaitEvent(0, F.ev_gemm, 0);
    k_gather<<<(n * 32 + 255) / 256, 256, 0, 0>>>(b, out, n);
}